// round 6
// baseline (speedup 1.0000x reference)
#include <cuda_runtime.h>
#include <cuda_bf16.h>
#include <cstdint>

// ExpertCapacityBuffer: N tokens, TOP_K=2, 64 experts.
// capacity = ceil(1.25*N*2/64). Flat slot-major: f = slot*N + tok.
// rank(f) = #{g<f : expert(g)==expert(f)}; keep iff rank < capacity.
//
// g_cnt rows: row r in [0,nbt) = slot0 of token-block r; row nbt+r = slot1.
// Row-major row order == flat order.
// Kernel 1 (count): per-row histograms; LAST block (done-counter) scans all
// rows into g_off (exclusive prefix per expert).
// Kernel 2 (apply): loads its two row offsets, computes in-block ranks, writes
// capped weights, indices, and overflow mask.

#define NE   64
#define TPB  1024
#define EPT  1024
#define MAXROWS 4096
#define NCH  16            // scan chunks

__device__ int g_cnt[MAXROWS][NE];
__device__ int g_off[MAXROWS][NE];
__device__ int g_done = 0;

// warp-0 dtype probe: int64 values <64 => odd 32-bit words zero (first 256B).
__device__ __forceinline__ void probe_w0(const void* eraw, int lane, int* s_is64) {
    if (threadIdx.x < 32) {
        unsigned x = ((const unsigned*)eraw)[2 * lane + 1];
        unsigned nz = __ballot_sync(0xFFFFFFFFu, x != 0u);
        if (lane == 0) *s_is64 = (nz == 0u);
    }
}

// ---------------- Kernel 1: histograms + last-block scan ----------------
__global__ void __launch_bounds__(TPB)
k_count(const void* __restrict__ eraw, int n_tok, int nbt) {
    __shared__ int hA[32][NE];
    __shared__ int hB[32][NE];
    __shared__ int s_is64;
    __shared__ int s_last;
    const int t = threadIdx.x, b = blockIdx.x;
    const int warp = t >> 5, lane = t & 31;

    const int tok = b * EPT + t;
    const bool valid = tok < n_tok;

    // eager int32-interpretation load (in-bounds for either dtype)
    int2 v32 = make_int2(0, 0);
    if (valid) v32 = __ldg((const int2*)eraw + tok);

    ((int*)hA)[t] = 0; ((int*)hA)[t + TPB] = 0;
    ((int*)hB)[t] = 0; ((int*)hB)[t + TPB] = 0;
    probe_w0(eraw, lane, &s_is64);
    __syncthreads();

    int e0 = NE + lane, e1 = NE + lane;      // unique keys for invalid lanes
    if (valid) {
        if (s_is64) {
            longlong2 v = __ldg((const longlong2*)eraw + tok);
            e0 = (int)v.x & (NE - 1); e1 = (int)v.y & (NE - 1);
        } else {
            e0 = v32.x & (NE - 1); e1 = v32.y & (NE - 1);
        }
    }
    unsigned m0 = __match_any_sync(0xFFFFFFFFu, e0);
    unsigned m1 = __match_any_sync(0xFFFFFFFFu, e1);
    unsigned lt = (1u << lane) - 1u;
    if (valid && !(m0 & lt)) hA[warp][e0] = __popc(m0);
    if (valid && !(m1 & lt)) hB[warp][e1] = __popc(m1);
    __syncthreads();

    if (t < NE) {
        int s = 0;
        #pragma unroll
        for (int w = 0; w < 32; w++) s += hA[w][t];
        g_cnt[b][t] = s;
    } else if (t < 2 * NE) {
        const int e = t - NE;
        int s = 0;
        #pragma unroll
        for (int w = 0; w < 32; w++) s += hB[w][e];
        g_cnt[nbt + b][e] = s;
    }
    __syncthreads();

    // ---- done-counter: last block performs the global scan
    if (t == 0) {
        __threadfence();
        s_last = (atomicAdd(&g_done, 1) == nbt - 1);
    }
    __syncthreads();
    if (!s_last) return;
    __threadfence();                    // acquire side of the message pass

    // scan 2*nbt rows, per expert: 16 chunks x 64 experts = 1024 threads
    {
        __shared__ int part[NCH][NE];
        const int rows = 2 * nbt;
        const int e = t & (NE - 1), c = t >> 6;
        const int rpc = (rows + NCH - 1) / NCH;   // <= 16 while rows <= 256
        const int r0 = c * rpc;

        if (rpc <= 16) {
            int vals[16];
            #pragma unroll
            for (int i = 0; i < 16; i++) {
                int r = r0 + i;
                vals[i] = (i < rpc && r < rows) ? g_cnt[r][e] : 0;
            }
            int s = 0;
            #pragma unroll
            for (int i = 0; i < 16; i++) s += vals[i];
            part[c][e] = s;
            __syncthreads();
            if (t < NE) {
                int run = 0;
                #pragma unroll
                for (int cc = 0; cc < NCH; cc++) { int v = part[cc][t]; part[cc][t] = run; run += v; }
            }
            __syncthreads();
            int run = part[c][e];
            #pragma unroll
            for (int i = 0; i < 16; i++) {
                int r = r0 + i;
                if (i < rpc && r < rows) { g_off[r][e] = run; run += vals[i]; }
            }
        } else {                         // generic fallback (large grids)
            int s = 0;
            for (int r = r0; r < min(r0 + rpc, rows); r++) s += g_cnt[r][e];
            part[c][e] = s;
            __syncthreads();
            if (t < NE) {
                int run = 0;
                #pragma unroll
                for (int cc = 0; cc < NCH; cc++) { int v = part[cc][t]; part[cc][t] = run; run += v; }
            }
            __syncthreads();
            int run = part[c][e];
            for (int r = r0; r < min(r0 + rpc, rows); r++) { int v = g_cnt[r][e]; g_off[r][e] = run; run += v; }
        }
    }
    if (t == 0) g_done = 0;             // reset for next graph replay
}

// ---------------- Kernel 2: ranks + outputs ----------------
// idx_mode: 0 none, 1 one-word (float), 2 int64
__global__ void __launch_bounds__(TPB)
k_apply(const float* __restrict__ w, const void* __restrict__ eraw,
        int n_tok, int capacity, int nbt,
        float* __restrict__ out_w, void* __restrict__ out_idx, int idx_mode,
        float* __restrict__ out_mask) {
    __shared__ int hA[32][NE];
    __shared__ int hB[32][NE];
    __shared__ int offA[NE], offB[NE];
    __shared__ int s_is64;
    const int t = threadIdx.x, b = blockIdx.x;
    const int warp = t >> 5, lane = t & 31;

    const int tok = b * EPT + t;
    const bool valid = tok < n_tok;

    // eager loads
    int2 v32 = make_int2(0, 0);
    float2 wv = make_float2(0.f, 0.f);
    if (valid) {
        v32 = __ldg((const int2*)eraw + tok);
        wv  = __ldg((const float2*)w + tok);
    }
    if (t < NE)          offA[t] = g_off[b][t];
    else if (t < 2 * NE) offB[t - NE] = g_off[nbt + b][t - NE];

    ((int*)hA)[t] = 0; ((int*)hA)[t + TPB] = 0;
    ((int*)hB)[t] = 0; ((int*)hB)[t + TPB] = 0;
    probe_w0(eraw, lane, &s_is64);
    __syncthreads();

    int e0 = NE + lane, e1 = NE + lane;
    if (valid) {
        if (s_is64) {
            longlong2 v = __ldg((const longlong2*)eraw + tok);
            e0 = (int)v.x & (NE - 1); e1 = (int)v.y & (NE - 1);
        } else {
            e0 = v32.x & (NE - 1); e1 = v32.y & (NE - 1);
        }
    }
    unsigned m0 = __match_any_sync(0xFFFFFFFFu, e0);
    unsigned m1 = __match_any_sync(0xFFFFFFFFu, e1);
    unsigned lt = (1u << lane) - 1u;
    const int wr0 = __popc(m0 & lt), wr1 = __popc(m1 & lt);
    if (valid && wr0 == 0) hA[warp][e0] = __popc(m0);
    if (valid && wr1 == 0) hB[warp][e1] = __popc(m1);
    __syncthreads();

    // threads 0-63: slot0 warp-scan; 64-127: slot1 (in parallel)
    if (t < NE) {
        int run = 0;
        #pragma unroll
        for (int ww = 0; ww < 32; ww++) { int v = hA[ww][t]; hA[ww][t] = run; run += v; }
    } else if (t < 2 * NE) {
        const int e = t - NE;
        int run = 0;
        #pragma unroll
        for (int ww = 0; ww < 32; ww++) { int v = hB[ww][e]; hB[ww][e] = run; run += v; }
    }
    __syncthreads();

    if (valid) {
        const int rank0 = offA[e0] + hA[warp][e0] + wr0;
        const int rank1 = offB[e1] + hB[warp][e1] + wr1;
        const float w0 = (rank0 < capacity) ? wv.x : 0.0f;
        const float w1 = (rank1 < capacity) ? wv.y : 0.0f;
        ((float2*)out_w)[tok] = make_float2(w0, w1);
        if (idx_mode == 1) {
            ((float2*)out_idx)[tok] = make_float2((float)e0, (float)e1);
        } else if (idx_mode == 2) {
            longlong2 iv; iv.x = e0; iv.y = e1;
            ((longlong2*)out_idx)[tok] = iv;
        }
        if (out_mask) out_mask[tok] = ((w0 + w1) == 0.0f) ? 1.0f : 0.0f;
    }
}

extern "C" void kernel_launch(void* const* d_in, const int* in_sizes, int n_in,
                              void* d_out, int out_size) {
    const float* w    = (const float*)d_in[0];
    const void*  eidx = d_in[1];

    int flat  = in_sizes[0];                 // N * TOP_K
    int n_tok = flat / 2;
    int capacity = (flat * 5 + 255) / 256;   // ceil(1.25 * flat / 64)
    if (capacity < 1) capacity = 1;
    int nbt = (n_tok + EPT - 1) / EPT;
    if (2 * nbt > MAXROWS) nbt = MAXROWS / 2;   // guard (not hit at these sizes)

    float* out = (float*)d_out;
    float* out_w    = out;
    void*  out_idx  = nullptr;
    float* out_mask = nullptr;
    int idx_mode = 0;

    if (out_size >= 3 * flat + n_tok) {          // weights + i64 indices + mask
        idx_mode = 2; out_idx = out + flat; out_mask = out + 3 * flat;
    } else if (out_size >= 2 * flat + n_tok) {   // weights + 1-word indices + mask
        idx_mode = 1; out_idx = out + flat; out_mask = out + 2 * flat;
    } else if (out_size >= flat + n_tok) {       // weights + mask
        out_mask = out + flat;
    }

    k_count<<<nbt, TPB>>>(eidx, n_tok, nbt);
    k_apply<<<nbt, TPB>>>(w, eidx, n_tok, capacity, nbt,
                          out_w, out_idx, idx_mode, out_mask);
}